// round 3
// baseline (speedup 1.0000x reference)
#include <cuda_runtime.h>
#include <math.h>

#define BQ 16
#define TQ 512
#define DQ 1024
#define FFQ 2048
#define EQ 4
#define CLSQ 1200
#define MQ (BQ*TQ)   // 8192

// ---------------- scratch (device globals; no allocation allowed) ------------
__device__ float g_h[(size_t)MQ * DQ];     // 32 MB  (fc1 out, then normed h)
__device__ float g_y1[(size_t)MQ * FFQ];   // 64 MB  (expert hidden, reused)
__device__ float g_moe[(size_t)MQ * DQ];   // 32 MB  (moe accumulation)
__device__ float g_gates[MQ * EQ];
__device__ float g_probs[MQ * EQ];
__device__ float g_sum[DQ];
__device__ float g_sumsq[DQ];
__device__ float g_scale[DQ];
__device__ float g_shift[DQ];

// ---------------- small helpers ---------------------------------------------
__device__ __forceinline__ float blockReduceSum256(float v, float* sh) {
    int tid = threadIdx.x;
    #pragma unroll
    for (int o = 16; o > 0; o >>= 1) v += __shfl_down_sync(0xffffffffu, v, o);
    if ((tid & 31) == 0) sh[tid >> 5] = v;
    __syncthreads();
    if (tid < 8) {
        float r = sh[tid];
        #pragma unroll
        for (int o = 4; o > 0; o >>= 1) r += __shfl_down_sync(0xffu, r, o);
        if (tid == 0) sh[0] = r;
    }
    __syncthreads();
    float r = sh[0];
    __syncthreads();
    return r;
}

__device__ __forceinline__ float blockReduceMax256(float v, float* sh) {
    int tid = threadIdx.x;
    #pragma unroll
    for (int o = 16; o > 0; o >>= 1) v = fmaxf(v, __shfl_down_sync(0xffffffffu, v, o));
    if ((tid & 31) == 0) sh[tid >> 5] = v;
    __syncthreads();
    if (tid < 8) {
        float r = sh[tid];
        #pragma unroll
        for (int o = 4; o > 0; o >>= 1) r = fmaxf(r, __shfl_down_sync(0xffu, r, o));
        if (tid == 0) sh[0] = r;
    }
    __syncthreads();
    float r = sh[0];
    __syncthreads();
    return r;
}

// ---------------- init: zero stats accumulators ------------------------------
__global__ void init_kernel() {
    int i = threadIdx.x;
    for (int d = i; d < DQ; d += 256) { g_sum[d] = 0.f; g_sumsq[d] = 0.f; }
}

// ---------------- generic conv/GEMM ------------------------------------------
// C[n, c] (epilogue) of sum_{kw, k} A[n + kw - KW/2 (within batch), k] * W[c, k, kw]
// W layout: [N][K][KW] row-major.  EPI: 0 = bias, 1 = relu(bias), 2 = moe accumulate
template<int KW, int EPI>
__global__ __launch_bounds__(256, 2)
void conv_gemm(const float* __restrict__ A, const float* __restrict__ W,
               const float* __restrict__ bias, float* __restrict__ C,
               const float* __restrict__ gates, int ecur, int accum,
               int N, int K)
{
    constexpr int HALO = KW / 2;
    constexpr int BM = 128, BN = 128, BK = 8;
    __shared__ float As[BK][BM + 2 * HALO + 2];   // +2 pad vs bank patterns
    __shared__ float Ws[KW][BK][BN];

    const int n0 = blockIdx.y * BM;
    const int c0 = blockIdx.x * BN;
    const int tid = threadIdx.x;
    const int ty = tid >> 4;          // 0..15 -> 8 rows each
    const int tx = tid & 15;          // 0..15 -> 8 cols each
    const int t_base = n0 % TQ;

    float acc[8][8];
    #pragma unroll
    for (int i = 0; i < 8; i++)
        #pragma unroll
        for (int j = 0; j < 8; j++) acc[i][j] = 0.f;

    for (int k0 = 0; k0 < K; k0 += BK) {
        // load A strip rows [n0-HALO, n0+BM-1+HALO]
        for (int i = tid; i < (BM + 2 * HALO) * BK; i += 256) {
            int s = i / BK, kk = i % BK;
            int t = t_base + s - HALO;
            float v = 0.f;
            if (t >= 0 && t < TQ)
                v = A[(size_t)(n0 + s - HALO) * K + k0 + kk];
            As[kk][s] = v;
        }
        // load W tile
        for (int i = tid; i < BN * BK * KW; i += 256) {
            int col = i / (BK * KW);
            int rem = i % (BK * KW);
            int kk = rem / KW, kw = rem % KW;
            int c = c0 + col;
            float w = 0.f;
            if (c < N) w = W[((size_t)c * K + k0 + kk) * KW + kw];
            Ws[kw][kk][col] = w;
        }
        __syncthreads();

        #pragma unroll
        for (int kk = 0; kk < BK; kk++) {
            float a[8 + 2 * HALO];
            #pragma unroll
            for (int i = 0; i < 8 + 2 * HALO; i++) a[i] = As[kk][ty * 8 + i];
            #pragma unroll
            for (int kw = 0; kw < KW; kw++) {
                float b[8];
                #pragma unroll
                for (int j = 0; j < 8; j++) b[j] = Ws[kw][kk][tx * 8 + j];
                #pragma unroll
                for (int i = 0; i < 8; i++)
                    #pragma unroll
                    for (int j = 0; j < 8; j++)
                        acc[i][j] = fmaf(a[i + kw], b[j], acc[i][j]);
            }
        }
        __syncthreads();
    }

    #pragma unroll
    for (int i = 0; i < 8; i++) {
        int n = n0 + ty * 8 + i;
        float g = 0.f;
        if (EPI == 2) g = gates[n * EQ + ecur];
        #pragma unroll
        for (int j = 0; j < 8; j++) {
            int c = c0 + tx * 8 + j;
            if (c < N) {
                float v = acc[i][j] + bias[c];
                if (EPI == 1) v = fmaxf(v, 0.f);
                size_t idx = (size_t)n * N + c;
                if (EPI == 2) {
                    v *= g;
                    if (accum) v += C[idx];
                }
                C[idx] = v;
            }
        }
    }
}

// ---------------- masked stats -----------------------------------------------
__global__ void stats_partial(const int* __restrict__ mask) {
    int d = blockIdx.y * 256 + threadIdx.x;
    int r0 = blockIdx.x * 256;
    float s = 0.f, s2 = 0.f;
    for (int r = 0; r < 256; r++) {
        int n = r0 + r;
        if (mask[n]) {
            float v = g_h[(size_t)n * DQ + d];
            s += v; s2 += v * v;
        }
    }
    atomicAdd(&g_sum[d], s);
    atomicAdd(&g_sumsq[d], s2);
}

__global__ void stats_final(const int* __restrict__ mask,
                            const float* __restrict__ bn_g,
                            const float* __restrict__ bn_b) {
    __shared__ float sh[32];
    __shared__ float s_cnt;
    int tid = threadIdx.x;  // 1024
    float c = 0.f;
    for (int n = tid; n < MQ; n += 1024) c += (float)mask[n];
    #pragma unroll
    for (int o = 16; o > 0; o >>= 1) c += __shfl_down_sync(0xffffffffu, c, o);
    if ((tid & 31) == 0) sh[tid >> 5] = c;
    __syncthreads();
    if (tid < 32) {
        c = sh[tid];
        #pragma unroll
        for (int o = 16; o > 0; o >>= 1) c += __shfl_down_sync(0xffffffffu, c, o);
        if (tid == 0) s_cnt = fmaxf(c, 1.f);
    }
    __syncthreads();
    float cnt = s_cnt;
    int d = tid;
    float mean = g_sum[d] / cnt;
    float var = g_sumsq[d] / cnt - mean * mean;
    var = fmaxf(var, 0.f);
    float sc = rsqrtf(var + 1e-5f) * bn_g[d];
    g_scale[d] = sc;
    g_shift[d] = bn_b[d] - mean * sc;
}

// ---------------- norm + relu + pe + gate ------------------------------------
__global__ void norm_gate(const int* __restrict__ mask,
                          const float* __restrict__ pe,
                          const float* __restrict__ gate_w) {
    int n = blockIdx.x;
    int t = n % TQ;
    int m = mask[n];
    int tid = threadIdx.x;
    float g0 = 0.f, g1 = 0.f, g2 = 0.f, g3 = 0.f;
    for (int d = tid; d < DQ; d += 256) {
        float v = g_h[(size_t)n * DQ + d];
        if (m) v = v * g_scale[d] + g_shift[d];
        v = fmaxf(v, 0.f) + pe[t * DQ + d];
        g_h[(size_t)n * DQ + d] = v;
        const float4 gw = *reinterpret_cast<const float4*>(gate_w + d * EQ);
        g0 += v * gw.x; g1 += v * gw.y; g2 += v * gw.z; g3 += v * gw.w;
    }
    __shared__ float sh[8][4];
    #pragma unroll
    for (int o = 16; o > 0; o >>= 1) {
        g0 += __shfl_down_sync(0xffffffffu, g0, o);
        g1 += __shfl_down_sync(0xffffffffu, g1, o);
        g2 += __shfl_down_sync(0xffffffffu, g2, o);
        g3 += __shfl_down_sync(0xffffffffu, g3, o);
    }
    if ((tid & 31) == 0) {
        int w = tid >> 5;
        sh[w][0] = g0; sh[w][1] = g1; sh[w][2] = g2; sh[w][3] = g3;
    }
    __syncthreads();
    if (tid == 0) {
        float l[4] = {0.f, 0.f, 0.f, 0.f};
        for (int w = 0; w < 8; w++)
            for (int e = 0; e < 4; e++) l[e] += sh[w][e];
        // dense softmax probs
        float mx = fmaxf(fmaxf(l[0], l[1]), fmaxf(l[2], l[3]));
        float ex[4], s = 0.f;
        for (int e = 0; e < 4; e++) { ex[e] = expf(l[e] - mx); s += ex[e]; }
        for (int e = 0; e < 4; e++) g_probs[n * EQ + e] = ex[e] / s;
        // top-2
        int i0 = 0;
        for (int e = 1; e < 4; e++) if (l[e] > l[i0]) i0 = e;
        int i1 = -1;
        for (int e = 0; e < 4; e++) {
            if (e == i0) continue;
            if (i1 < 0 || l[e] > l[i1]) i1 = e;
        }
        float ee = expf(l[i1] - l[i0]);
        float ga = 1.f / (1.f + ee);
        float gb = ee / (1.f + ee);
        float gt[4] = {0.f, 0.f, 0.f, 0.f};
        gt[i0] = ga; gt[i1] = gb;
        for (int e = 0; e < 4; e++) g_gates[n * EQ + e] = gt[e];
    }
}

// ---------------- LayerNorm + feat + feat_norm -------------------------------
__global__ void ln_kernel(const float* __restrict__ ln_g,
                          const float* __restrict__ ln_b,
                          float* __restrict__ feat,
                          float* __restrict__ featn) {
    __shared__ float sh[8];
    int n = blockIdx.x;
    int tid = threadIdx.x;
    float v[4];
    float s = 0.f;
    #pragma unroll
    for (int i = 0; i < 4; i++) {
        int d = tid + i * 256;
        v[i] = g_moe[(size_t)n * DQ + d];
        s += v[i];
    }
    float mu = blockReduceSum256(s, sh) * (1.f / DQ);
    float q = 0.f;
    #pragma unroll
    for (int i = 0; i < 4; i++) { float dd = v[i] - mu; q += dd * dd; }
    float var = blockReduceSum256(q, sh) * (1.f / DQ);
    float r = rsqrtf(var + 1e-6f);
    float f[4];
    float ss = 0.f;
    #pragma unroll
    for (int i = 0; i < 4; i++) {
        int d = tid + i * 256;
        f[i] = (v[i] - mu) * r * ln_g[d] + ln_b[d];
        feat[(size_t)n * DQ + d] = f[i];
        ss += f[i] * f[i];
    }
    float nrm = fmaxf(sqrtf(blockReduceSum256(ss, sh)), 1e-12f);
    float inv = 1.f / nrm;
    #pragma unroll
    for (int i = 0; i < 4; i++) {
        int d = tid + i * 256;
        featn[(size_t)n * DQ + d] = f[i] * inv;
    }
}

// ---------------- log-softmax over classes -----------------------------------
__global__ void softmax_kernel(const float* __restrict__ logits,
                               float* __restrict__ logp,
                               float* __restrict__ p) {
    __shared__ float sh[8];
    int n = blockIdx.x;
    int tid = threadIdx.x;
    const float* row = logits + (size_t)n * CLSQ;
    float mx = -1e30f;
    for (int c = tid; c < CLSQ; c += 256) mx = fmaxf(mx, row[c]);
    mx = blockReduceMax256(mx, sh);
    float s = 0.f;
    for (int c = tid; c < CLSQ; c += 256) s += expf(row[c] - mx);
    s = blockReduceSum256(s, sh);
    float lse = mx + logf(s);
    for (int c = tid; c < CLSQ; c += 256) {
        float lp = row[c] - lse;
        logp[(size_t)n * CLSQ + c] = lp;
        p[(size_t)n * CLSQ + c] = expf(lp);
    }
}

// ---------------- aux loss ---------------------------------------------------
__global__ void aux_kernel(float* __restrict__ out_aux) {
    __shared__ float sh[8];
    int tid = threadIdx.x;
    float imp[4] = {0.f, 0.f, 0.f, 0.f};
    float frc[4] = {0.f, 0.f, 0.f, 0.f};
    for (int n = tid; n < MQ; n += 256) {
        #pragma unroll
        for (int e = 0; e < 4; e++) {
            imp[e] += g_probs[n * EQ + e];
            frc[e] += (g_gates[n * EQ + e] > 0.f) ? 1.f : 0.f;
        }
    }
    float tot[8];
    #pragma unroll
    for (int e = 0; e < 4; e++) tot[e] = blockReduceSum256(imp[e], sh);
    #pragma unroll
    for (int e = 0; e < 4; e++) tot[4 + e] = blockReduceSum256(frc[e], sh);
    if (tid == 0) {
        float aux = 0.f;
        for (int e = 0; e < 4; e++)
            aux += (tot[4 + e] / (float)MQ) * (tot[e] / (float)MQ);
        out_aux[0] = (float)EQ * aux;
    }
}

// ---------------- host orchestration -----------------------------------------
extern "C" void kernel_launch(void* const* d_in, const int* in_sizes, int n_in,
                              void* d_out, int out_size) {
    const float* x      = (const float*)d_in[0];
    const int*   mask   = (const int*)  d_in[1];
    const float* fc1_w  = (const float*)d_in[2];
    const float* fc1_b  = (const float*)d_in[3];
    const float* bn_g   = (const float*)d_in[4];
    const float* bn_b   = (const float*)d_in[5];
    const float* pe     = (const float*)d_in[6];
    const float* gate_w = (const float*)d_in[7];
    const float* ew1    = (const float*)d_in[8];
    const float* eb1    = (const float*)d_in[9];
    const float* ew2    = (const float*)d_in[10];
    const float* eb2    = (const float*)d_in[11];
    const float* ln_g   = (const float*)d_in[12];
    const float* ln_b   = (const float*)d_in[13];
    const float* out_w  = (const float*)d_in[14];
    const float* out_b  = (const float*)d_in[15];

    float* out = (float*)d_out;
    const size_t FEAT = (size_t)MQ * DQ;       // 8388608
    const size_t LGT  = (size_t)MQ * CLSQ;     // 9830400
    float* feat   = out;
    float* featn  = out + FEAT;
    float* logits = out + 2 * FEAT;
    float* logp   = logits + LGT;
    float* p      = logp + LGT;
    float* aux    = p + LGT;

    float *h, *y1, *moe, *gates;
    cudaGetSymbolAddress((void**)&h,    g_h);
    cudaGetSymbolAddress((void**)&y1,   g_y1);
    cudaGetSymbolAddress((void**)&moe,  g_moe);
    cudaGetSymbolAddress((void**)&gates, g_gates);

    init_kernel<<<1, 256>>>();

    // fc1: h = x @ fc1_w^T + b
    conv_gemm<1, 0><<<dim3(DQ / 128, MQ / 128), 256>>>(
        x, fc1_w, fc1_b, h, nullptr, 0, 0, DQ, DQ);

    stats_partial<<<dim3(32, 4), 256>>>(mask);
    stats_final<<<1, 1024>>>(mask, bn_g, bn_b);
    norm_gate<<<MQ, 256>>>(mask, pe, gate_w);

    for (int e = 0; e < EQ; e++) {
        conv_gemm<3, 1><<<dim3(FFQ / 128, MQ / 128), 256>>>(
            h, ew1 + (size_t)e * FFQ * DQ * 3, eb1 + e * FFQ, y1,
            nullptr, 0, 0, FFQ, DQ);
        conv_gemm<3, 2><<<dim3(DQ / 128, MQ / 128), 256>>>(
            y1, ew2 + (size_t)e * DQ * FFQ * 3, eb2 + e * DQ, moe,
            gates, e, (e > 0) ? 1 : 0, DQ, FFQ);
    }

    ln_kernel<<<MQ, 256>>>(ln_g, ln_b, feat, featn);

    conv_gemm<1, 0><<<dim3((CLSQ + 127) / 128, MQ / 128), 256>>>(
        feat, out_w, out_b, logits, nullptr, 0, 0, CLSQ, DQ);

    softmax_kernel<<<MQ, 256>>>(logits, logp, p);
    aux_kernel<<<1, 256>>>(aux);
}

// round 8
// speedup vs baseline: 3.2862x; 3.2862x over previous
#include <cuda_runtime.h>
#include <cuda_bf16.h>
#include <math.h>
#include <stdint.h>

typedef __nv_bfloat16 bf16;

#define BQ 16
#define TQ 512
#define DQ 1024
#define FFQ 2048
#define EQ 4
#define CLSQ 1200
#define MQ (BQ*TQ)

// GEMM tiling
#define GBM 128
#define GBN 128
#define GBK 32
#define A_LO_OFF 10240
#define B_HI_OFF 20480
#define B_LO_OFF 30720
#define STAGE_BYTES 40960
#define SMEM_GEMM (2*STAGE_BYTES)   // 81920

__device__ float g_h[(size_t)MQ * DQ];
__device__ float g_moe[(size_t)MQ * DQ];
__device__ float g_gates[MQ * EQ];
__device__ float g_probs[MQ * EQ];
__device__ float g_sum[DQ];
__device__ float g_sumsq[DQ];
__device__ float g_scale[DQ];
__device__ float g_shift[DQ];

__device__ bf16 g_xh[(size_t)MQ * DQ],  g_xl[(size_t)MQ * DQ];
__device__ bf16 g_hh[(size_t)MQ * DQ],  g_hl[(size_t)MQ * DQ];
__device__ bf16 g_y1h[(size_t)MQ * FFQ], g_y1l[(size_t)MQ * FFQ];
__device__ bf16 g_fh[(size_t)MQ * DQ],  g_fl[(size_t)MQ * DQ];
__device__ bf16 g_w1h[(size_t)EQ * FFQ * 3 * DQ],  g_w1l[(size_t)EQ * FFQ * 3 * DQ];
__device__ bf16 g_w2h[(size_t)EQ * DQ * 3 * FFQ],  g_w2l[(size_t)EQ * DQ * 3 * FFQ];
__device__ bf16 g_fc1h[DQ * DQ], g_fc1l[DQ * DQ];
__device__ bf16 g_owh[CLSQ * DQ], g_owl[CLSQ * DQ];

__device__ __forceinline__ uint32_t smem_u32(const void* p) {
    uint32_t a;
    asm("{ .reg .u64 t; cvta.to.shared.u64 t, %1; cvt.u32.u64 %0, t; }" : "=r"(a) : "l"(p));
    return a;
}
__device__ __forceinline__ void cp16(uint32_t dst, const void* src, int pred) {
    int sz = pred ? 16 : 0;
    asm volatile("cp.async.cg.shared.global [%0], [%1], 16, %2;"
                 :: "r"(dst), "l"(src), "r"(sz));
}
__device__ __forceinline__ void ldsm4(uint32_t* r, uint32_t addr) {
    asm volatile("ldmatrix.sync.aligned.m8n8.x4.shared.b16 {%0,%1,%2,%3}, [%4];"
                 : "=r"(r[0]), "=r"(r[1]), "=r"(r[2]), "=r"(r[3]) : "r"(addr));
}
__device__ __forceinline__ void mma16816(float* d, const uint32_t* a, const uint32_t* b) {
    asm volatile(
        "mma.sync.aligned.m16n8k16.row.col.f32.bf16.bf16.f32 "
        "{%0,%1,%2,%3}, {%4,%5,%6,%7}, {%8,%9}, {%0,%1,%2,%3};"
        : "+f"(d[0]), "+f"(d[1]), "+f"(d[2]), "+f"(d[3])
        : "r"(a[0]), "r"(a[1]), "r"(a[2]), "r"(a[3]), "r"(b[0]), "r"(b[1]));
}
__device__ __forceinline__ uint32_t pk2(bf16 a, bf16 b) {
    __nv_bfloat162 t = __halves2bfloat162(a, b);
    return *reinterpret_cast<uint32_t*>(&t);
}

// C[m,c] = sum_{k'} A[m+shift(k'), kcol] * W[c,k']   (hi/lo bf16, 3-pass HMMA)
// EPI 0: Cf = acc+bias (guard c<Nrows)
// EPI 1: relu(acc+bias) -> Coh/Col (bf16 hi/lo)
// EPI 2: (acc+bias)*gate[m,ecur] (+Cf if accum) -> Cf
template<int EPI>
__global__ __launch_bounds__(256, 1)
void gemm_hmma(const bf16* __restrict__ Ah, const bf16* __restrict__ Al,
               const bf16* __restrict__ Bh, const bf16* __restrict__ Bl,
               const float* __restrict__ bias,
               float* __restrict__ Cf, bf16* __restrict__ Coh, bf16* __restrict__ Col,
               const float* __restrict__ gates, int ecur, int accum,
               int Nrows, int Kseg, int KW, int strideA)
{
    extern __shared__ char smem[];
    const int tid = threadIdx.x;
    const int lane = tid & 31;
    const int wid = tid >> 5;
    const int wr = wid >> 2;      // 0..1 (m)
    const int wc = wid & 3;       // 0..3 (n)
    const int m0 = blockIdx.y * GBM;
    const int c0 = blockIdx.x * GBN;
    const int K = Kseg * KW;
    const int KT = K >> 5;
    const int HALO = KW >> 1;
    const uint32_t sb = smem_u32(smem);

    float acc[4][4][4];
    #pragma unroll
    for (int i = 0; i < 4; i++)
        #pragma unroll
        for (int j = 0; j < 4; j++)
            #pragma unroll
            for (int k = 0; k < 4; k++) acc[i][j][k] = 0.f;

    auto load_stage = [&](int stage, int kt) {
        const int k0 = kt * GBK;
        const int kw = k0 / Kseg;
        const int kcol = k0 - kw * Kseg;
        const int dt = kw - HALO;
        const uint32_t ss = sb + stage * STAGE_BYTES;
        #pragma unroll
        for (int i = 0; i < 2; i++) {
            int idx = i * 256 + tid;
            int r = idx >> 2, c = idx & 3;
            int m = m0 + r;
            int t = (m & (TQ - 1)) + dt;
            int pr = (t >= 0) && (t < TQ);
            size_t off = (size_t)(m + dt) * strideA + kcol + c * 8;
            const bf16* sh = pr ? (Ah + off) : Ah;
            const bf16* sl = pr ? (Al + off) : Al;
            uint32_t d = ss + r * 80 + c * 16;
            cp16(d, sh, pr);
            cp16(d + A_LO_OFF, sl, pr);
        }
        #pragma unroll
        for (int i = 0; i < 2; i++) {
            int idx = i * 256 + tid;
            int r = idx >> 2, c = idx & 3;
            int n = c0 + r;
            int pr = n < Nrows;
            size_t off = (size_t)n * K + k0 + c * 8;
            const bf16* sh = pr ? (Bh + off) : Bh;
            const bf16* sl = pr ? (Bl + off) : Bl;
            uint32_t d = ss + B_HI_OFF + r * 80 + c * 16;
            cp16(d, sh, pr);
            cp16(d + (B_LO_OFF - B_HI_OFF), sl, pr);
        }
        asm volatile("cp.async.commit_group;" ::: "memory");
    };

    load_stage(0, 0);

    const int arow = wr * 64 + (lane & 15);            // + mi*16
    const uint32_t achunk = (lane & 16) ? 16u : 0u;    // + ks*32
    const int brow = wc * 32 + (lane & 7) + ((lane & 16) ? 8 : 0);  // + nb*16
    const uint32_t bchunk = (lane & 8) ? 16u : 0u;

    for (int kt = 0; kt < KT; kt++) {
        const uint32_t cs = sb + (kt & 1) * STAGE_BYTES;
        asm volatile("cp.async.wait_group 0;" ::: "memory");
        __syncthreads();
        if (kt + 1 < KT) load_stage((kt + 1) & 1, kt + 1);

        #pragma unroll
        for (int ks = 0; ks < 2; ks++) {
            uint32_t ah[4][4], al[4][4], bh[4][2], bl[4][2];
            #pragma unroll
            for (int mi = 0; mi < 4; mi++) {
                uint32_t ad = cs + (arow + mi * 16) * 80 + ks * 32 + achunk;
                ldsm4(ah[mi], ad);
                ldsm4(al[mi], ad + A_LO_OFF);
            }
            #pragma unroll
            for (int nb = 0; nb < 2; nb++) {
                uint32_t tmp[4];
                uint32_t bd = cs + B_HI_OFF + (brow + nb * 16) * 80 + ks * 32 + bchunk;
                ldsm4(tmp, bd);
                bh[nb * 2][0] = tmp[0]; bh[nb * 2][1] = tmp[1];
                bh[nb * 2 + 1][0] = tmp[2]; bh[nb * 2 + 1][1] = tmp[3];
                ldsm4(tmp, bd + (B_LO_OFF - B_HI_OFF));
                bl[nb * 2][0] = tmp[0]; bl[nb * 2][1] = tmp[1];
                bl[nb * 2 + 1][0] = tmp[2]; bl[nb * 2 + 1][1] = tmp[3];
            }
            #pragma unroll
            for (int mi = 0; mi < 4; mi++)
                #pragma unroll
                for (int ni = 0; ni < 4; ni++) {
                    mma16816(acc[mi][ni], ah[mi], bh[ni]);
                    mma16816(acc[mi][ni], ah[mi], bl[ni]);
                    mma16816(acc[mi][ni], al[mi], bh[ni]);
                }
        }
        __syncthreads();
    }

    // epilogue: direct register -> gmem
    #pragma unroll
    for (int mi = 0; mi < 4; mi++) {
        int r0 = m0 + wr * 64 + mi * 16 + (lane >> 2);
        int r1 = r0 + 8;
        float gg0 = 0.f, gg1 = 0.f;
        if (EPI == 2) {
            gg0 = gates[r0 * EQ + ecur];
            gg1 = gates[r1 * EQ + ecur];
        }
        #pragma unroll
        for (int ni = 0; ni < 4; ni++) {
            int c = c0 + wc * 32 + ni * 8 + (lane & 3) * 2;
            if (c >= Nrows) continue;
            float2 bv = *reinterpret_cast<const float2*>(bias + c);
            float* a = acc[mi][ni];
            float v0 = a[0] + bv.x, v1 = a[1] + bv.y;
            float v2 = a[2] + bv.x, v3 = a[3] + bv.y;
            if (EPI == 0) {
                *reinterpret_cast<float2*>(Cf + (size_t)r0 * Nrows + c) = make_float2(v0, v1);
                *reinterpret_cast<float2*>(Cf + (size_t)r1 * Nrows + c) = make_float2(v2, v3);
            } else if (EPI == 1) {
                v0 = fmaxf(v0, 0.f); v1 = fmaxf(v1, 0.f);
                v2 = fmaxf(v2, 0.f); v3 = fmaxf(v3, 0.f);
                bf16 h0 = __float2bfloat16(v0), h1 = __float2bfloat16(v1);
                bf16 h2 = __float2bfloat16(v2), h3 = __float2bfloat16(v3);
                bf16 l0 = __float2bfloat16(v0 - __bfloat162float(h0));
                bf16 l1 = __float2bfloat16(v1 - __bfloat162float(h1));
                bf16 l2 = __float2bfloat16(v2 - __bfloat162float(h2));
                bf16 l3 = __float2bfloat16(v3 - __bfloat162float(h3));
                *reinterpret_cast<uint32_t*>(Coh + (size_t)r0 * Nrows + c) = pk2(h0, h1);
                *reinterpret_cast<uint32_t*>(Coh + (size_t)r1 * Nrows + c) = pk2(h2, h3);
                *reinterpret_cast<uint32_t*>(Col + (size_t)r0 * Nrows + c) = pk2(l0, l1);
                *reinterpret_cast<uint32_t*>(Col + (size_t)r1 * Nrows + c) = pk2(l2, l3);
            } else {
                v0 *= gg0; v1 *= gg0; v2 *= gg1; v3 *= gg1;
                if (accum) {
                    float2 o0 = *reinterpret_cast<const float2*>(Cf + (size_t)r0 * Nrows + c);
                    float2 o1 = *reinterpret_cast<const float2*>(Cf + (size_t)r1 * Nrows + c);
                    v0 += o0.x; v1 += o0.y; v2 += o1.x; v3 += o1.y;
                }
                *reinterpret_cast<float2*>(Cf + (size_t)r0 * Nrows + c) = make_float2(v0, v1);
                *reinterpret_cast<float2*>(Cf + (size_t)r1 * Nrows + c) = make_float2(v2, v3);
            }
        }
    }
}

__global__ void split_kernel(const float* __restrict__ src, bf16* __restrict__ h,
                             bf16* __restrict__ l, int n) {
    int i = blockIdx.x * 256 + threadIdx.x;
    if (i < n) {
        float v = src[i];
        bf16 hh = __float2bfloat16(v);
        h[i] = hh;
        l[i] = __float2bfloat16(v - __bfloat162float(hh));
    }
}
// [rows][Kseg][KW] -> [rows][KW][Kseg]
__global__ void perm_kernel(const float* __restrict__ w, bf16* __restrict__ h,
                            bf16* __restrict__ l, int rows, int Kseg) {
    int i = blockIdx.x * 256 + threadIdx.x;
    if (i >= rows * 3 * Kseg) return;
    int row = i / (3 * Kseg);
    int rem = i - row * 3 * Kseg;
    int kw = rem / Kseg, d = rem - kw * Kseg;
    float v = w[(size_t)row * 3 * Kseg + (size_t)d * 3 + kw];
    bf16 hh = __float2bfloat16(v);
    h[i] = hh;
    l[i] = __float2bfloat16(v - __bfloat162float(hh));
}

__device__ __forceinline__ float blockReduceSum256(float v, float* sh) {
    int tid = threadIdx.x;
    #pragma unroll
    for (int o = 16; o > 0; o >>= 1) v += __shfl_down_sync(0xffffffffu, v, o);
    if ((tid & 31) == 0) sh[tid >> 5] = v;
    __syncthreads();
    if (tid < 8) {
        float r = sh[tid];
        #pragma unroll
        for (int o = 4; o > 0; o >>= 1) r += __shfl_down_sync(0xffu, r, o);
        if (tid == 0) sh[0] = r;
    }
    __syncthreads();
    float r = sh[0];
    __syncthreads();
    return r;
}
__device__ __forceinline__ float blockReduceMax256(float v, float* sh) {
    int tid = threadIdx.x;
    #pragma unroll
    for (int o = 16; o > 0; o >>= 1) v = fmaxf(v, __shfl_down_sync(0xffffffffu, v, o));
    if ((tid & 31) == 0) sh[tid >> 5] = v;
    __syncthreads();
    if (tid < 8) {
        float r = sh[tid];
        #pragma unroll
        for (int o = 4; o > 0; o >>= 1) r = fmaxf(r, __shfl_down_sync(0xffu, r, o));
        if (tid == 0) sh[0] = r;
    }
    __syncthreads();
    float r = sh[0];
    __syncthreads();
    return r;
}

__global__ void init_kernel() {
    int i = threadIdx.x;
    for (int d = i; d < DQ; d += 256) { g_sum[d] = 0.f; g_sumsq[d] = 0.f; }
}

__global__ void stats_partial(const int* __restrict__ mask) {
    int d = blockIdx.y * 256 + threadIdx.x;
    int r0 = blockIdx.x * 256;
    float s = 0.f, s2 = 0.f;
    for (int r = 0; r < 256; r++) {
        int n = r0 + r;
        if (mask[n]) {
            float v = g_h[(size_t)n * DQ + d];
            s += v; s2 += v * v;
        }
    }
    atomicAdd(&g_sum[d], s);
    atomicAdd(&g_sumsq[d], s2);
}

__global__ void stats_final(const int* __restrict__ mask,
                            const float* __restrict__ bn_g,
                            const float* __restrict__ bn_b) {
    __shared__ float sh[32];
    __shared__ float s_cnt;
    int tid = threadIdx.x;  // 1024
    float c = 0.f;
    for (int n = tid; n < MQ; n += 1024) c += (float)mask[n];
    #pragma unroll
    for (int o = 16; o > 0; o >>= 1) c += __shfl_down_sync(0xffffffffu, c, o);
    if ((tid & 31) == 0) sh[tid >> 5] = c;
    __syncthreads();
    if (tid < 32) {
        c = sh[tid];
        #pragma unroll
        for (int o = 16; o > 0; o >>= 1) c += __shfl_down_sync(0xffffffffu, c, o);
        if (tid == 0) s_cnt = fmaxf(c, 1.f);
    }
    __syncthreads();
    float cnt = s_cnt;
    int d = tid;
    float mean = g_sum[d] / cnt;
    float var = fmaxf(g_sumsq[d] / cnt - mean * mean, 0.f);
    float sc = rsqrtf(var + 1e-5f) * bn_g[d];
    g_scale[d] = sc;
    g_shift[d] = bn_b[d] - mean * sc;
}

__global__ void norm_gate(const int* __restrict__ mask,
                          const float* __restrict__ pe,
                          const float* __restrict__ gate_w) {
    int n = blockIdx.x;
    int t = n % TQ;
    int m = mask[n];
    int tid = threadIdx.x;
    float g0 = 0.f, g1 = 0.f, g2 = 0.f, g3 = 0.f;
    for (int d = tid; d < DQ; d += 256) {
        float v = g_h[(size_t)n * DQ + d];
        if (m) v = v * g_scale[d] + g_shift[d];
        v = fmaxf(v, 0.f) + pe[t * DQ + d];
        bf16 hh = __float2bfloat16(v);
        g_hh[(size_t)n * DQ + d] = hh;
        g_hl[(size_t)n * DQ + d] = __float2bfloat16(v - __bfloat162float(hh));
        const float4 gw = *reinterpret_cast<const float4*>(gate_w + d * EQ);
        g0 += v * gw.x; g1 += v * gw.y; g2 += v * gw.z; g3 += v * gw.w;
    }
    __shared__ float sh[8][4];
    #pragma unroll
    for (int o = 16; o > 0; o >>= 1) {
        g0 += __shfl_down_sync(0xffffffffu, g0, o);
        g1 += __shfl_down_sync(0xffffffffu, g1, o);
        g2 += __shfl_down_sync(0xffffffffu, g2, o);
        g3 += __shfl_down_sync(0xffffffffu, g3, o);
    }
    if ((tid & 31) == 0) {
        int w = tid >> 5;
        sh[w][0] = g0; sh[w][1] = g1; sh[w][2] = g2; sh[w][3] = g3;
    }
    __syncthreads();
    if (tid == 0) {
        float l[4] = {0.f, 0.f, 0.f, 0.f};
        for (int w = 0; w < 8; w++)
            for (int e = 0; e < 4; e++) l[e] += sh[w][e];
        float mx = fmaxf(fmaxf(l[0], l[1]), fmaxf(l[2], l[3]));
        float ex[4], s = 0.f;
        for (int e = 0; e < 4; e++) { ex[e] = expf(l[e] - mx); s += ex[e]; }
        for (int e = 0; e < 4; e++) g_probs[n * EQ + e] = ex[e] / s;
        int i0 = 0;
        for (int e = 1; e < 4; e++) if (l[e] > l[i0]) i0 = e;
        int i1 = -1;
        for (int e = 0; e < 4; e++) {
            if (e == i0) continue;
            if (i1 < 0 || l[e] > l[i1]) i1 = e;
        }
        float ee = expf(l[i1] - l[i0]);
        float gt[4] = {0.f, 0.f, 0.f, 0.f};
        gt[i0] = 1.f / (1.f + ee);
        gt[i1] = ee / (1.f + ee);
        for (int e = 0; e < 4; e++) g_gates[n * EQ + e] = gt[e];
    }
}

__global__ void ln_kernel(const float* __restrict__ ln_g,
                          const float* __restrict__ ln_b,
                          float* __restrict__ feat,
                          float* __restrict__ featn) {
    __shared__ float sh[8];
    int n = blockIdx.x;
    int tid = threadIdx.x;
    float v[4];
    float s = 0.f;
    #pragma unroll
    for (int i = 0; i < 4; i++) {
        int d = tid + i * 256;
        v[i] = g_moe[(size_t)n * DQ + d];
        s += v[i];
    }
    float mu = blockReduceSum256(s, sh) * (1.f / DQ);
    float q = 0.f;
    #pragma unroll
    for (int i = 0; i < 4; i++) { float dd = v[i] - mu; q += dd * dd; }
    float var = blockReduceSum256(q, sh) * (1.f / DQ);
    float r = rsqrtf(var + 1e-6f);
    float f[4];
    float ss = 0.f;
    #pragma unroll
    for (int i = 0; i < 4; i++) {
        int d = tid + i * 256;
        f[i] = (v[i] - mu) * r * ln_g[d] + ln_b[d];
        feat[(size_t)n * DQ + d] = f[i];
        bf16 hh = __float2bfloat16(f[i]);
        g_fh[(size_t)n * DQ + d] = hh;
        g_fl[(size_t)n * DQ + d] = __float2bfloat16(f[i] - __bfloat162float(hh));
        ss += f[i] * f[i];
    }
    float nrm = fmaxf(sqrtf(blockReduceSum256(ss, sh)), 1e-12f);
    float inv = 1.f / nrm;
    #pragma unroll
    for (int i = 0; i < 4; i++) {
        int d = tid + i * 256;
        featn[(size_t)n * DQ + d] = f[i] * inv;
    }
}

__global__ void softmax_kernel(const float* __restrict__ logits,
                               float* __restrict__ logp,
                               float* __restrict__ p) {
    __shared__ float sh[8];
    int n = blockIdx.x;
    int tid = threadIdx.x;
    const float* row = logits + (size_t)n * CLSQ;
    float mx = -1e30f;
    for (int c = tid; c < CLSQ; c += 256) mx = fmaxf(mx, row[c]);
    mx = blockReduceMax256(mx, sh);
    float s = 0.f;
    for (int c = tid; c < CLSQ; c += 256) s += expf(row[c] - mx);
    s = blockReduceSum256(s, sh);
    float lse = mx + logf(s);
    for (int c = tid; c < CLSQ; c += 256) {
        float lp = row[c] - lse;
        logp[(size_t)n * CLSQ + c] = lp;
        p[(size_t)n * CLSQ + c] = expf(lp);
    }
}

__global__ void aux_kernel(float* __restrict__ out_aux) {
    __shared__ float sh[8];
    int tid = threadIdx.x;
    float imp[4] = {0.f, 0.f, 0.f, 0.f};
    float frc[4] = {0.f, 0.f, 0.f, 0.f};
    for (int n = tid; n < MQ; n += 256) {
        #pragma unroll
        for (int e = 0; e < 4; e++) {
            imp[e] += g_probs[n * EQ + e];
            frc[e] += (g_gates[n * EQ + e] > 0.f) ? 1.f : 0.f;
        }
    }
    float tot[8];
    #pragma unroll
    for (int e = 0; e < 4; e++) tot[e] = blockReduceSum256(imp[e], sh);
    #pragma unroll
    for (int e = 0; e < 4; e++) tot[4 + e] = blockReduceSum256(frc[e], sh);
    if (tid == 0) {
        float aux = 0.f;
        for (int e = 0; e < 4; e++)
            aux += (tot[4 + e] / (float)MQ) * (tot[e] / (float)MQ);
        out_aux[0] = (float)EQ * aux;
    }
}

extern "C" void kernel_launch(void* const* d_in, const int* in_sizes, int n_in,
                              void* d_out, int out_size) {
    const float* x      = (const float*)d_in[0];
    const int*   mask   = (const int*)  d_in[1];
    const float* fc1_w  = (const float*)d_in[2];
    const float* fc1_b  = (const float*)d_in[3];
    const float* bn_g   = (const float*)d_in[4];
    const float* bn_b   = (const float*)d_in[5];
    const float* pe     = (const float*)d_in[6];
    const float* gate_w = (const float*)d_in[7];
    const float* ew1    = (const float*)d_in[8];
    const float* eb1    = (const float*)d_in[9];
    const float* ew2    = (const float*)d_in[10];
    const float* eb2    = (const float*)d_in[11];
    const float* ln_g   = (const float*)d_in[12];
    const float* ln_b   = (const float*)d_in[13];
    const float* out_w  = (const float*)d_in[14];
    const float* out_b  = (const float*)d_in[15];

    float* out = (float*)d_out;
    const size_t FEAT = (size_t)MQ * DQ;
    const size_t LGT  = (size_t)MQ * CLSQ;
    float* feat   = out;
    float* featn  = out + FEAT;
    float* logits = out + 2 * FEAT;
    float* logp   = logits + LGT;
    float* p      = logp + LGT;
    float* aux    = p + LGT;

    float *h, *moe, *gates;
    bf16 *xh, *xl, *hh, *hl, *y1h, *y1l, *fh, *fl;
    bf16 *w1h, *w1l, *w2h, *w2l, *fc1h, *fc1l, *owh, *owl;
    cudaGetSymbolAddress((void**)&h,     g_h);
    cudaGetSymbolAddress((void**)&moe,   g_moe);
    cudaGetSymbolAddress((void**)&gates, g_gates);
    cudaGetSymbolAddress((void**)&xh,  g_xh);   cudaGetSymbolAddress((void**)&xl,  g_xl);
    cudaGetSymbolAddress((void**)&hh,  g_hh);   cudaGetSymbolAddress((void**)&hl,  g_hl);
    cudaGetSymbolAddress((void**)&y1h, g_y1h);  cudaGetSymbolAddress((void**)&y1l, g_y1l);
    cudaGetSymbolAddress((void**)&fh,  g_fh);   cudaGetSymbolAddress((void**)&fl,  g_fl);
    cudaGetSymbolAddress((void**)&w1h, g_w1h);  cudaGetSymbolAddress((void**)&w1l, g_w1l);
    cudaGetSymbolAddress((void**)&w2h, g_w2h);  cudaGetSymbolAddress((void**)&w2l, g_w2l);
    cudaGetSymbolAddress((void**)&fc1h, g_fc1h); cudaGetSymbolAddress((void**)&fc1l, g_fc1l);
    cudaGetSymbolAddress((void**)&owh, g_owh);  cudaGetSymbolAddress((void**)&owl, g_owl);

    cudaFuncSetAttribute(gemm_hmma<0>, cudaFuncAttributeMaxDynamicSharedMemorySize, SMEM_GEMM);
    cudaFuncSetAttribute(gemm_hmma<1>, cudaFuncAttributeMaxDynamicSharedMemorySize, SMEM_GEMM);
    cudaFuncSetAttribute(gemm_hmma<2>, cudaFuncAttributeMaxDynamicSharedMemorySize, SMEM_GEMM);

    init_kernel<<<1, 256>>>();

    split_kernel<<<(MQ * DQ) / 256, 256>>>(x, xh, xl, MQ * DQ);
    split_kernel<<<(DQ * DQ) / 256, 256>>>(fc1_w, fc1h, fc1l, DQ * DQ);
    split_kernel<<<(CLSQ * DQ) / 256, 256>>>(out_w, owh, owl, CLSQ * DQ);
    perm_kernel<<<(EQ * FFQ * 3 * DQ) / 256, 256>>>(ew1, w1h, w1l, EQ * FFQ, DQ);
    perm_kernel<<<(EQ * DQ * 3 * FFQ) / 256, 256>>>(ew2, w2h, w2l, EQ * DQ, FFQ);

    // fc1: [MQ,DQ] x [DQ,DQ]^T
    gemm_hmma<0><<<dim3(DQ / GBN, MQ / GBM), 256, SMEM_GEMM>>>(
        xh, xl, fc1h, fc1l, fc1_b, h, nullptr, nullptr, nullptr, 0, 0, DQ, DQ, 1, DQ);

    stats_partial<<<dim3(32, 4), 256>>>(mask);
    stats_final<<<1, 1024>>>(mask, bn_g, bn_b);
    norm_gate<<<MQ, 256>>>(mask, pe, gate_w);

    for (int e = 0; e < EQ; e++) {
        gemm_hmma<1><<<dim3(FFQ / GBN, MQ / GBM), 256, SMEM_GEMM>>>(
            hh, hl, w1h + (size_t)e * FFQ * 3 * DQ, w1l + (size_t)e * FFQ * 3 * DQ,
            eb1 + e * FFQ, nullptr, y1h, y1l, nullptr, 0, 0, FFQ, DQ, 3, DQ);
        gemm_hmma<2><<<dim3(DQ / GBN, MQ / GBM), 256, SMEM_GEMM>>>(
            y1h, y1l, w2h + (size_t)e * DQ * 3 * FFQ, w2l + (size_t)e * DQ * 3 * FFQ,
            eb2 + e * DQ, moe, nullptr, nullptr, gates, e, (e > 0) ? 1 : 0, DQ, FFQ, 3, FFQ);
    }

    ln_kernel<<<MQ, 256>>>(ln_g, ln_b, feat, featn);

    gemm_hmma<0><<<dim3((CLSQ + GBN - 1) / GBN, MQ / GBM), 256, SMEM_GEMM>>>(
        fh, fl, owh, owl, out_b, logits, nullptr, nullptr, nullptr, 0, 0, CLSQ, DQ, 1, DQ);

    softmax_kernel<<<MQ, 256>>>(logits, logp, p);
    aux_kernel<<<1, 256>>>(aux);
}

// round 11
// speedup vs baseline: 4.9582x; 1.5088x over previous
#include <cuda_runtime.h>
#include <cuda_bf16.h>
#include <math.h>
#include <stdint.h>

typedef __nv_bfloat16 bf16;

#define BQ 16
#define TQ 512
#define DQ 1024
#define FFQ 2048
#define EQ 4
#define CLSQ 1200
#define MQ (BQ*TQ)

// GEMM tiling
#define GBM 128
#define GBN 128
#define GBK 32
#define A_LO_OFF 10240
#define B_HI_OFF 20480
#define B_LO_OFF 30720
#define STAGE_BYTES 40960
#define SMEM_GEMM (2*STAGE_BYTES)   // 81920

__device__ float g_h[(size_t)MQ * DQ];
__device__ float g_moe[(size_t)MQ * DQ];
__device__ float g_gates[MQ * EQ];
__device__ float g_probs[MQ * EQ];
__device__ float g_sum[DQ];
__device__ float g_sumsq[DQ];
__device__ float g_scale[DQ];
__device__ float g_shift[DQ];

__device__ int g_selidx[EQ * MQ];
__device__ int g_dilidx[EQ * MQ];
__device__ int g_selcnt[EQ];
__device__ int g_dilcnt[EQ];

__device__ bf16 g_xh[(size_t)MQ * DQ],  g_xl[(size_t)MQ * DQ];
__device__ bf16 g_hh[(size_t)MQ * DQ],  g_hl[(size_t)MQ * DQ];
__device__ bf16 g_y1h[(size_t)MQ * FFQ], g_y1l[(size_t)MQ * FFQ];
__device__ bf16 g_fh[(size_t)MQ * DQ],  g_fl[(size_t)MQ * DQ];
__device__ bf16 g_w1h[(size_t)EQ * FFQ * 3 * DQ],  g_w1l[(size_t)EQ * FFQ * 3 * DQ];
__device__ bf16 g_w2h[(size_t)EQ * DQ * 3 * FFQ],  g_w2l[(size_t)EQ * DQ * 3 * FFQ];
__device__ bf16 g_fc1h[DQ * DQ], g_fc1l[DQ * DQ];
__device__ bf16 g_owh[CLSQ * DQ], g_owl[CLSQ * DQ];

__device__ __forceinline__ uint32_t smem_u32(const void* p) {
    uint32_t a;
    asm("{ .reg .u64 t; cvta.to.shared.u64 t, %1; cvt.u32.u64 %0, t; }" : "=r"(a) : "l"(p));
    return a;
}
__device__ __forceinline__ void cp16(uint32_t dst, const void* src, int pred) {
    int sz = pred ? 16 : 0;
    asm volatile("cp.async.cg.shared.global [%0], [%1], 16, %2;"
                 :: "r"(dst), "l"(src), "r"(sz));
}
__device__ __forceinline__ void ldsm4(uint32_t* r, uint32_t addr) {
    asm volatile("ldmatrix.sync.aligned.m8n8.x4.shared.b16 {%0,%1,%2,%3}, [%4];"
                 : "=r"(r[0]), "=r"(r[1]), "=r"(r[2]), "=r"(r[3]) : "r"(addr));
}
__device__ __forceinline__ void mma16816(float* d, const uint32_t* a, const uint32_t* b) {
    asm volatile(
        "mma.sync.aligned.m16n8k16.row.col.f32.bf16.bf16.f32 "
        "{%0,%1,%2,%3}, {%4,%5,%6,%7}, {%8,%9}, {%0,%1,%2,%3};"
        : "+f"(d[0]), "+f"(d[1]), "+f"(d[2]), "+f"(d[3])
        : "r"(a[0]), "r"(a[1]), "r"(a[2]), "r"(a[3]), "r"(b[0]), "r"(b[1]));
}
__device__ __forceinline__ uint32_t pk2(bf16 a, bf16 b) {
    __nv_bfloat162 t = __halves2bfloat162(a, b);
    return *reinterpret_cast<uint32_t*>(&t);
}

// C[m,c] = sum_{k'} A[m+shift(k'), kcol] * W[c,k']   (hi/lo bf16, 3-pass HMMA)
// USE_IDX: tile rows gathered through idxlist (count at *cntptr); padding predicated.
// EPI 0: Cf = acc+bias (guard c<Nrows)
// EPI 1: relu(acc+bias) -> Coh/Col (bf16 hi/lo), rows scattered by idx
// EPI 2: (acc+bias)*gate[m,ecur] (+Cf if accum) -> Cf, rows scattered by idx
template<int EPI, int USE_IDX>
__global__ __launch_bounds__(256, 1)
void gemm_hmma(const bf16* __restrict__ Ah, const bf16* __restrict__ Al,
               const bf16* __restrict__ Bh, const bf16* __restrict__ Bl,
               const float* __restrict__ bias,
               float* __restrict__ Cf, bf16* __restrict__ Coh, bf16* __restrict__ Col,
               const float* __restrict__ gates, int ecur, int accum,
               const int* __restrict__ idxlist, const int* __restrict__ cntptr,
               int Nrows, int Kseg, int KW, int strideA)
{
    extern __shared__ char smem[];
    __shared__ int sidx[GBM];
    const int tid = threadIdx.x;
    const int lane = tid & 31;
    const int wid = tid >> 5;
    const int wr = wid >> 2;      // 0..1 (m)
    const int wc = wid & 3;       // 0..3 (n)
    const int m0 = blockIdx.y * GBM;
    const int c0 = blockIdx.x * GBN;
    const int K = Kseg * KW;
    const int KT = K >> 5;
    const int HALO = KW >> 1;
    const uint32_t sb = smem_u32(smem);

    int cnt = 0x7fffffff;
    if (USE_IDX) {
        cnt = cntptr[0];
        if (m0 >= cnt) return;
        if (tid < GBM) {
            int gi = m0 + tid;
            sidx[tid] = (gi < cnt) ? idxlist[gi] : -1;
        }
        __syncthreads();
    }

    float acc[4][4][4];
    #pragma unroll
    for (int i = 0; i < 4; i++)
        #pragma unroll
        for (int j = 0; j < 4; j++)
            #pragma unroll
            for (int k = 0; k < 4; k++) acc[i][j][k] = 0.f;

    auto load_stage = [&](int stage, int kt) {
        const int k0 = kt * GBK;
        const int kw = k0 / Kseg;
        const int kcol = k0 - kw * Kseg;
        const int dt = kw - HALO;
        const uint32_t ss = sb + stage * STAGE_BYTES;
        #pragma unroll
        for (int i = 0; i < 2; i++) {
            int idx = i * 256 + tid;
            int r = idx >> 2, c = idx & 3;
            int m, valid;
            if (USE_IDX) { m = sidx[r]; valid = (m >= 0); }
            else { m = m0 + r; valid = 1; }
            int t = (m & (TQ - 1)) + dt;
            int pr = valid && (t >= 0) && (t < TQ);
            int msafe = pr ? (m + dt) : 0;
            size_t off = (size_t)msafe * strideA + kcol + c * 8;
            uint32_t d = ss + r * 80 + c * 16;
            cp16(d, Ah + off, pr);
            cp16(d + A_LO_OFF, Al + off, pr);
        }
        #pragma unroll
        for (int i = 0; i < 2; i++) {
            int idx = i * 256 + tid;
            int r = idx >> 2, c = idx & 3;
            int n = c0 + r;
            int pr = n < Nrows;
            size_t off = pr ? ((size_t)n * K + k0 + c * 8) : 0;
            uint32_t d = ss + B_HI_OFF + r * 80 + c * 16;
            cp16(d, Bh + off, pr);
            cp16(d + (B_LO_OFF - B_HI_OFF), Bl + off, pr);
        }
        asm volatile("cp.async.commit_group;" ::: "memory");
    };

    load_stage(0, 0);

    const int arow = wr * 64 + (lane & 15);            // + mi*16
    const uint32_t achunk = (lane & 16) ? 16u : 0u;    // + ks*32
    const int brow = wc * 32 + (lane & 7) + ((lane & 16) ? 8 : 0);  // + nb*16
    const uint32_t bchunk = (lane & 8) ? 16u : 0u;

    for (int kt = 0; kt < KT; kt++) {
        const uint32_t cs = sb + (kt & 1) * STAGE_BYTES;
        asm volatile("cp.async.wait_group 0;" ::: "memory");
        __syncthreads();
        if (kt + 1 < KT) load_stage((kt + 1) & 1, kt + 1);

        #pragma unroll
        for (int ks = 0; ks < 2; ks++) {
            uint32_t ah[4][4], al[4][4], bh[4][2], bl[4][2];
            #pragma unroll
            for (int mi = 0; mi < 4; mi++) {
                uint32_t ad = cs + (arow + mi * 16) * 80 + ks * 32 + achunk;
                ldsm4(ah[mi], ad);
                ldsm4(al[mi], ad + A_LO_OFF);
            }
            #pragma unroll
            for (int nb = 0; nb < 2; nb++) {
                uint32_t tmp[4];
                uint32_t bd = cs + B_HI_OFF + (brow + nb * 16) * 80 + ks * 32 + bchunk;
                ldsm4(tmp, bd);
                bh[nb * 2][0] = tmp[0]; bh[nb * 2][1] = tmp[1];
                bh[nb * 2 + 1][0] = tmp[2]; bh[nb * 2 + 1][1] = tmp[3];
                ldsm4(tmp, bd + (B_LO_OFF - B_HI_OFF));
                bl[nb * 2][0] = tmp[0]; bl[nb * 2][1] = tmp[1];
                bl[nb * 2 + 1][0] = tmp[2]; bl[nb * 2 + 1][1] = tmp[3];
            }
            #pragma unroll
            for (int mi = 0; mi < 4; mi++)
                #pragma unroll
                for (int ni = 0; ni < 4; ni++) {
                    mma16816(acc[mi][ni], ah[mi], bh[ni]);
                    mma16816(acc[mi][ni], ah[mi], bl[ni]);
                    mma16816(acc[mi][ni], al[mi], bh[ni]);
                }
        }
        __syncthreads();
    }

    // epilogue: direct register -> gmem (rows via idx when USE_IDX)
    #pragma unroll
    for (int mi = 0; mi < 4; mi++) {
        int lr0 = wr * 64 + mi * 16 + (lane >> 2);
        int lr1 = lr0 + 8;
        int r0, r1, v0, v1;
        if (USE_IDX) {
            r0 = sidx[lr0]; r1 = sidx[lr1];
            v0 = (r0 >= 0); v1 = (r1 >= 0);
            if (r0 < 0) r0 = 0;
            if (r1 < 0) r1 = 0;
        } else {
            r0 = m0 + lr0; r1 = m0 + lr1; v0 = 1; v1 = 1;
        }
        float gg0 = 0.f, gg1 = 0.f;
        if (EPI == 2) {
            if (v0) gg0 = gates[r0 * EQ + ecur];
            if (v1) gg1 = gates[r1 * EQ + ecur];
        }
        #pragma unroll
        for (int ni = 0; ni < 4; ni++) {
            int c = c0 + wc * 32 + ni * 8 + (lane & 3) * 2;
            if (c >= Nrows) continue;
            float2 bv = *reinterpret_cast<const float2*>(bias + c);
            float* a = acc[mi][ni];
            float w0 = a[0] + bv.x, w1 = a[1] + bv.y;
            float w2 = a[2] + bv.x, w3 = a[3] + bv.y;
            if (EPI == 0) {
                if (v0) *reinterpret_cast<float2*>(Cf + (size_t)r0 * Nrows + c) = make_float2(w0, w1);
                if (v1) *reinterpret_cast<float2*>(Cf + (size_t)r1 * Nrows + c) = make_float2(w2, w3);
            } else if (EPI == 1) {
                w0 = fmaxf(w0, 0.f); w1 = fmaxf(w1, 0.f);
                w2 = fmaxf(w2, 0.f); w3 = fmaxf(w3, 0.f);
                bf16 h0 = __float2bfloat16(w0), h1 = __float2bfloat16(w1);
                bf16 h2 = __float2bfloat16(w2), h3 = __float2bfloat16(w3);
                bf16 l0 = __float2bfloat16(w0 - __bfloat162float(h0));
                bf16 l1 = __float2bfloat16(w1 - __bfloat162float(h1));
                bf16 l2 = __float2bfloat16(w2 - __bfloat162float(h2));
                bf16 l3 = __float2bfloat16(w3 - __bfloat162float(h3));
                if (v0) {
                    *reinterpret_cast<uint32_t*>(Coh + (size_t)r0 * Nrows + c) = pk2(h0, h1);
                    *reinterpret_cast<uint32_t*>(Col + (size_t)r0 * Nrows + c) = pk2(l0, l1);
                }
                if (v1) {
                    *reinterpret_cast<uint32_t*>(Coh + (size_t)r1 * Nrows + c) = pk2(h2, h3);
                    *reinterpret_cast<uint32_t*>(Col + (size_t)r1 * Nrows + c) = pk2(l2, l3);
                }
            } else {
                w0 *= gg0; w1 *= gg0; w2 *= gg1; w3 *= gg1;
                if (accum) {
                    if (v0) {
                        float2 o0 = *reinterpret_cast<const float2*>(Cf + (size_t)r0 * Nrows + c);
                        w0 += o0.x; w1 += o0.y;
                    }
                    if (v1) {
                        float2 o1 = *reinterpret_cast<const float2*>(Cf + (size_t)r1 * Nrows + c);
                        w2 += o1.x; w3 += o1.y;
                    }
                }
                if (v0) *reinterpret_cast<float2*>(Cf + (size_t)r0 * Nrows + c) = make_float2(w0, w1);
                if (v1) *reinterpret_cast<float2*>(Cf + (size_t)r1 * Nrows + c) = make_float2(w2, w3);
            }
        }
    }
}

__global__ void split_kernel(const float* __restrict__ src, bf16* __restrict__ h,
                             bf16* __restrict__ l, int n) {
    int i = blockIdx.x * 256 + threadIdx.x;
    if (i < n) {
        float v = src[i];
        bf16 hh = __float2bfloat16(v);
        h[i] = hh;
        l[i] = __float2bfloat16(v - __bfloat162float(hh));
    }
}
// [rows][Kseg][KW] -> [rows][KW][Kseg]
__global__ void perm_kernel(const float* __restrict__ w, bf16* __restrict__ h,
                            bf16* __restrict__ l, int rows, int Kseg) {
    int i = blockIdx.x * 256 + threadIdx.x;
    if (i >= rows * 3 * Kseg) return;
    int row = i / (3 * Kseg);
    int rem = i - row * 3 * Kseg;
    int kw = rem / Kseg, d = rem - kw * Kseg;
    float v = w[(size_t)row * 3 * Kseg + (size_t)d * 3 + kw];
    bf16 hh = __float2bfloat16(v);
    h[i] = hh;
    l[i] = __float2bfloat16(v - __bfloat162float(hh));
}

__global__ void zero_moe() {
    size_t i = (size_t)blockIdx.x * 256 + threadIdx.x;
    reinterpret_cast<float4*>(g_moe)[i] = make_float4(0.f, 0.f, 0.f, 0.f);
}

// per-expert sorted index lists: selected (gate>0) and dilated (neighbor window)
__global__ void build_idx() {
    int e = blockIdx.x;
    int tid = threadIdx.x;   // 256
    __shared__ int ss[256], sd[256];
    int base = tid * 32;
    uint32_t selm = 0, dilm = 0;
    for (int i = 0; i < 32; i++) {
        int n = base + i;
        int t = n & (TQ - 1);
        bool sel = g_gates[n * EQ + e] > 0.f;
        bool dil = sel;
        if (t > 0) dil = dil || (g_gates[(n - 1) * EQ + e] > 0.f);
        if (t < TQ - 1) dil = dil || (g_gates[(n + 1) * EQ + e] > 0.f);
        if (sel) selm |= (1u << i);
        if (dil) dilm |= (1u << i);
    }
    int cs = __popc(selm), cd = __popc(dilm);
    ss[tid] = cs; sd[tid] = cd;
    __syncthreads();
    for (int o = 1; o < 256; o <<= 1) {
        int vs = (tid >= o) ? ss[tid - o] : 0;
        int vd = (tid >= o) ? sd[tid - o] : 0;
        __syncthreads();
        ss[tid] += vs; sd[tid] += vd;
        __syncthreads();
    }
    int ps = ss[tid] - cs, pd = sd[tid] - cd;
    for (int i = 0; i < 32; i++) {
        int n = base + i;
        if (selm & (1u << i)) g_selidx[e * MQ + ps++] = n;
        if (dilm & (1u << i)) g_dilidx[e * MQ + pd++] = n;
    }
    if (tid == 255) { g_selcnt[e] = ss[255]; g_dilcnt[e] = sd[255]; }
}

__device__ __forceinline__ float blockReduceSum256(float v, float* sh) {
    int tid = threadIdx.x;
    #pragma unroll
    for (int o = 16; o > 0; o >>= 1) v += __shfl_down_sync(0xffffffffu, v, o);
    if ((tid & 31) == 0) sh[tid >> 5] = v;
    __syncthreads();
    if (tid < 8) {
        float r = sh[tid];
        #pragma unroll
        for (int o = 4; o > 0; o >>= 1) r += __shfl_down_sync(0xffu, r, o);
        if (tid == 0) sh[0] = r;
    }
    __syncthreads();
    float r = sh[0];
    __syncthreads();
    return r;
}
__device__ __forceinline__ float blockReduceMax256(float v, float* sh) {
    int tid = threadIdx.x;
    #pragma unroll
    for (int o = 16; o > 0; o >>= 1) v = fmaxf(v, __shfl_down_sync(0xffffffffu, v, o));
    if ((tid & 31) == 0) sh[tid >> 5] = v;
    __syncthreads();
    if (tid < 8) {
        float r = sh[tid];
        #pragma unroll
        for (int o = 4; o > 0; o >>= 1) r = fmaxf(r, __shfl_down_sync(0xffu, r, o));
        if (tid == 0) sh[0] = r;
    }
    __syncthreads();
    float r = sh[0];
    __syncthreads();
    return r;
}

__global__ void init_kernel() {
    int i = threadIdx.x;
    for (int d = i; d < DQ; d += 256) { g_sum[d] = 0.f; g_sumsq[d] = 0.f; }
}

__global__ void stats_partial(const int* __restrict__ mask) {
    int d = blockIdx.y * 256 + threadIdx.x;
    int r0 = blockIdx.x * 256;
    float s = 0.f, s2 = 0.f;
    for (int r = 0; r < 256; r++) {
        int n = r0 + r;
        if (mask[n]) {
            float v = g_h[(size_t)n * DQ + d];
            s += v; s2 += v * v;
        }
    }
    atomicAdd(&g_sum[d], s);
    atomicAdd(&g_sumsq[d], s2);
}

__global__ void stats_final(const int* __restrict__ mask,
                            const float* __restrict__ bn_g,
                            const float* __restrict__ bn_b) {
    __shared__ float sh[32];
    __shared__ float s_cnt;
    int tid = threadIdx.x;  // 1024
    float c = 0.f;
    for (int n = tid; n < MQ; n += 1024) c += (float)mask[n];
    #pragma unroll
    for (int o = 16; o > 0; o >>= 1) c += __shfl_down_sync(0xffffffffu, c, o);
    if ((tid & 31) == 0) sh[tid >> 5] = c;
    __syncthreads();
    if (tid < 32) {
        c = sh[tid];
        #pragma unroll
        for (int o = 16; o > 0; o >>= 1) c += __shfl_down_sync(0xffffffffu, c, o);
        if (tid == 0) s_cnt = fmaxf(c, 1.f);
    }
    __syncthreads();
    float cnt = s_cnt;
    int d = tid;
    float mean = g_sum[d] / cnt;
    float var = fmaxf(g_sumsq[d] / cnt - mean * mean, 0.f);
    float sc = rsqrtf(var + 1e-5f) * bn_g[d];
    g_scale[d] = sc;
    g_shift[d] = bn_b[d] - mean * sc;
}

__global__ void norm_gate(const int* __restrict__ mask,
                          const float* __restrict__ pe,
                          const float* __restrict__ gate_w) {
    int n = blockIdx.x;
    int t = n % TQ;
    int m = mask[n];
    int tid = threadIdx.x;
    float g0 = 0.f, g1 = 0.f, g2 = 0.f, g3 = 0.f;
    for (int d = tid; d < DQ; d += 256) {
        float v = g_h[(size_t)n * DQ + d];
        if (m) v = v * g_scale[d] + g_shift[d];
        v = fmaxf(v, 0.f) + pe[t * DQ + d];
        bf16 hh = __float2bfloat16(v);
        g_hh[(size_t)n * DQ + d] = hh;
        g_hl[(size_t)n * DQ + d] = __float2bfloat16(v - __bfloat162float(hh));
        const float4 gw = *reinterpret_cast<const float4*>(gate_w + d * EQ);
        g0 += v * gw.x; g1 += v * gw.y; g2 += v * gw.z; g3 += v * gw.w;
    }
    __shared__ float sh[8][4];
    #pragma unroll
    for (int o = 16; o > 0; o >>= 1) {
        g0 += __shfl_down_sync(0xffffffffu, g0, o);
        g1 += __shfl_down_sync(0xffffffffu, g1, o);
        g2 += __shfl_down_sync(0xffffffffu, g2, o);
        g3 += __shfl_down_sync(0xffffffffu, g3, o);
    }
    if ((tid & 31) == 0) {
        int w = tid >> 5;
        sh[w][0] = g0; sh[w][1] = g1; sh[w][2] = g2; sh[w][3] = g3;
    }
    __syncthreads();
    if (tid == 0) {
        float l[4] = {0.f, 0.f, 0.f, 0.f};
        for (int w = 0; w < 8; w++)
            for (int e = 0; e < 4; e++) l[e] += sh[w][e];
        float mx = fmaxf(fmaxf(l[0], l[1]), fmaxf(l[2], l[3]));
        float ex[4], s = 0.f;
        for (int e = 0; e < 4; e++) { ex[e] = expf(l[e] - mx); s += ex[e]; }
        for (int e = 0; e < 4; e++) g_probs[n * EQ + e] = ex[e] / s;
        int i0 = 0;
        for (int e = 1; e < 4; e++) if (l[e] > l[i0]) i0 = e;
        int i1 = -1;
        for (int e = 0; e < 4; e++) {
            if (e == i0) continue;
            if (i1 < 0 || l[e] > l[i1]) i1 = e;
        }
        float ee = expf(l[i1] - l[i0]);
        float gt[4] = {0.f, 0.f, 0.f, 0.f};
        gt[i0] = 1.f / (1.f + ee);
        gt[i1] = ee / (1.f + ee);
        for (int e = 0; e < 4; e++) g_gates[n * EQ + e] = gt[e];
    }
}

__global__ void ln_kernel(const float* __restrict__ ln_g,
                          const float* __restrict__ ln_b,
                          float* __restrict__ feat,
                          float* __restrict__ featn) {
    __shared__ float sh[8];
    int n = blockIdx.x;
    int tid = threadIdx.x;
    float v[4];
    float s = 0.f;
    #pragma unroll
    for (int i = 0; i < 4; i++) {
        int d = tid + i * 256;
        v[i] = g_moe[(size_t)n * DQ + d];
        s += v[i];
    }
    float mu = blockReduceSum256(s, sh) * (1.f / DQ);
    float q = 0.f;
    #pragma unroll
    for (int i = 0; i < 4; i++) { float dd = v[i] - mu; q += dd * dd; }
    float var = blockReduceSum256(q, sh) * (1.f / DQ);
    float r = rsqrtf(var + 1e-6f);
    float f[4];
    float ss = 0.f;
    #pragma unroll
    for (int i = 0; i < 4; i++) {
        int d = tid + i * 256;
        f[i] = (v[i] - mu) * r * ln_g[d] + ln_b[d];
        feat[(size_t)n * DQ + d] = f[i];
        bf16 hh = __float2bfloat16(f[i]);
        g_fh[(size_t)n * DQ + d] = hh;
        g_fl[(size_t)n * DQ + d] = __float2bfloat16(f[i] - __bfloat162float(hh));
        ss += f[i] * f[i];
    }
    float nrm = fmaxf(sqrtf(blockReduceSum256(ss, sh)), 1e-12f);
    float inv = 1.f / nrm;
    #pragma unroll
    for (int i = 0; i < 4; i++) {
        int d = tid + i * 256;
        featn[(size_t)n * DQ + d] = f[i] * inv;
    }
}

__global__ void softmax_kernel(const float* __restrict__ logits,
                               float* __restrict__ logp,
                               float* __restrict__ p) {
    __shared__ float sh[8];
    int n = blockIdx.x;
    int tid = threadIdx.x;
    const float* row = logits + (size_t)n * CLSQ;
    float mx = -1e30f;
    for (int c = tid; c < CLSQ; c += 256) mx = fmaxf(mx, row[c]);
    mx = blockReduceMax256(mx, sh);
    float s = 0.f;
    for (int c = tid; c < CLSQ; c += 256) s += expf(row[c] - mx);
    s = blockReduceSum256(s, sh);
    float lse = mx + logf(s);
    for (int c = tid; c < CLSQ; c += 256) {
        float lp = row[c] - lse;
        logp[(size_t)n * CLSQ + c] = lp;
        p[(size_t)n * CLSQ + c] = expf(lp);
    }
}

__global__ void aux_kernel(float* __restrict__ out_aux) {
    __shared__ float sh[8];
    int tid = threadIdx.x;
    float imp[4] = {0.f, 0.f, 0.f, 0.f};
    float frc[4] = {0.f, 0.f, 0.f, 0.f};
    for (int n = tid; n < MQ; n += 256) {
        #pragma unroll
        for (int e = 0; e < 4; e++) {
            imp[e] += g_probs[n * EQ + e];
            frc[e] += (g_gates[n * EQ + e] > 0.f) ? 1.f : 0.f;
        }
    }
    float tot[8];
    #pragma unroll
    for (int e = 0; e < 4; e++) tot[e] = blockReduceSum256(imp[e], sh);
    #pragma unroll
    for (int e = 0; e < 4; e++) tot[4 + e] = blockReduceSum256(frc[e], sh);
    if (tid == 0) {
        float aux = 0.f;
        for (int e = 0; e < 4; e++)
            aux += (tot[4 + e] / (float)MQ) * (tot[e] / (float)MQ);
        out_aux[0] = (float)EQ * aux;
    }
}

extern "C" void kernel_launch(void* const* d_in, const int* in_sizes, int n_in,
                              void* d_out, int out_size) {
    const float* x      = (const float*)d_in[0];
    const int*   mask   = (const int*)  d_in[1];
    const float* fc1_w  = (const float*)d_in[2];
    const float* fc1_b  = (const float*)d_in[3];
    const float* bn_g   = (const float*)d_in[4];
    const float* bn_b   = (const float*)d_in[5];
    const float* pe     = (const float*)d_in[6];
    const float* gate_w = (const float*)d_in[7];
    const float* ew1    = (const float*)d_in[8];
    const float* eb1    = (const float*)d_in[9];
    const float* ew2    = (const float*)d_in[10];
    const float* eb2    = (const float*)d_in[11];
    const float* ln_g   = (const float*)d_in[12];
    const float* ln_b   = (const float*)d_in[13];
    const float* out_w  = (const float*)d_in[14];
    const float* out_b  = (const float*)d_in[15];

    float* out = (float*)d_out;
    const size_t FEAT = (size_t)MQ * DQ;
    const size_t LGT  = (size_t)MQ * CLSQ;
    float* feat   = out;
    float* featn  = out + FEAT;
    float* logits = out + 2 * FEAT;
    float* logp   = logits + LGT;
    float* p      = logp + LGT;
    float* aux    = p + LGT;

    float *h, *moe, *gates;
    bf16 *xh, *xl, *hh, *hl, *y1h, *y1l, *fh, *fl;
    bf16 *w1h, *w1l, *w2h, *w2l, *fc1h, *fc1l, *owh, *owl;
    int *selidx, *dilidx, *selcnt, *dilcnt;
    cudaGetSymbolAddress((void**)&h,     g_h);
    cudaGetSymbolAddress((void**)&moe,   g_moe);
    cudaGetSymbolAddress((void**)&gates, g_gates);
    cudaGetSymbolAddress((void**)&xh,  g_xh);   cudaGetSymbolAddress((void**)&xl,  g_xl);
    cudaGetSymbolAddress((void**)&hh,  g_hh);   cudaGetSymbolAddress((void**)&hl,  g_hl);
    cudaGetSymbolAddress((void**)&y1h, g_y1h);  cudaGetSymbolAddress((void**)&y1l, g_y1l);
    cudaGetSymbolAddress((void**)&fh,  g_fh);   cudaGetSymbolAddress((void**)&fl,  g_fl);
    cudaGetSymbolAddress((void**)&w1h, g_w1h);  cudaGetSymbolAddress((void**)&w1l, g_w1l);
    cudaGetSymbolAddress((void**)&w2h, g_w2h);  cudaGetSymbolAddress((void**)&w2l, g_w2l);
    cudaGetSymbolAddress((void**)&fc1h, g_fc1h); cudaGetSymbolAddress((void**)&fc1l, g_fc1l);
    cudaGetSymbolAddress((void**)&owh, g_owh);  cudaGetSymbolAddress((void**)&owl, g_owl);
    cudaGetSymbolAddress((void**)&selidx, g_selidx);
    cudaGetSymbolAddress((void**)&dilidx, g_dilidx);
    cudaGetSymbolAddress((void**)&selcnt, g_selcnt);
    cudaGetSymbolAddress((void**)&dilcnt, g_dilcnt);

    cudaFuncSetAttribute(gemm_hmma<0,0>, cudaFuncAttributeMaxDynamicSharedMemorySize, SMEM_GEMM);
    cudaFuncSetAttribute(gemm_hmma<1,1>, cudaFuncAttributeMaxDynamicSharedMemorySize, SMEM_GEMM);
    cudaFuncSetAttribute(gemm_hmma<2,1>, cudaFuncAttributeMaxDynamicSharedMemorySize, SMEM_GEMM);

    init_kernel<<<1, 256>>>();

    split_kernel<<<(MQ * DQ) / 256, 256>>>(x, xh, xl, MQ * DQ);
    split_kernel<<<(DQ * DQ) / 256, 256>>>(fc1_w, fc1h, fc1l, DQ * DQ);
    split_kernel<<<(CLSQ * DQ) / 256, 256>>>(out_w, owh, owl, CLSQ * DQ);
    perm_kernel<<<(EQ * FFQ * 3 * DQ) / 256, 256>>>(ew1, w1h, w1l, EQ * FFQ, DQ);
    perm_kernel<<<(EQ * DQ * 3 * FFQ) / 256, 256>>>(ew2, w2h, w2l, EQ * DQ, FFQ);

    // fc1: [MQ,DQ] x [DQ,DQ]^T
    gemm_hmma<0,0><<<dim3(DQ / GBN, MQ / GBM), 256, SMEM_GEMM>>>(
        xh, xl, fc1h, fc1l, fc1_b, h, nullptr, nullptr, nullptr, 0, 0,
        nullptr, nullptr, DQ, DQ, 1, DQ);

    stats_partial<<<dim3(32, 4), 256>>>(mask);
    stats_final<<<1, 1024>>>(mask, bn_g, bn_b);
    norm_gate<<<MQ, 256>>>(mask, pe, gate_w);
    build_idx<<<EQ, 256>>>();
    zero_moe<<<(MQ * DQ / 4) / 256, 256>>>();

    for (int e = 0; e < EQ; e++) {
        // conv1 on dilated token set (rows gathered; y1 scattered dense)
        gemm_hmma<1,1><<<dim3(FFQ / GBN, MQ / GBM), 256, SMEM_GEMM>>>(
            hh, hl, w1h + (size_t)e * FFQ * 3 * DQ, w1l + (size_t)e * FFQ * 3 * DQ,
            eb1 + e * FFQ, nullptr, y1h, y1l, nullptr, 0, 0,
            dilidx + e * MQ, dilcnt + e, FFQ, DQ, 3, DQ);
        // conv2 on selected token set, gate-scaled accumulate into moe
        gemm_hmma<2,1><<<dim3(DQ / GBN, MQ / GBM), 256, SMEM_GEMM>>>(
            y1h, y1l, w2h + (size_t)e * DQ * 3 * FFQ, w2l + (size_t)e * DQ * 3 * FFQ,
            eb2 + e * DQ, moe, nullptr, nullptr, gates, e, 1,
            selidx + e * MQ, selcnt + e, DQ, FFQ, 3, FFQ);
    }

    ln_kernel<<<MQ, 256>>>(ln_g, ln_b, feat, featn);

    gemm_hmma<0,0><<<dim3((CLSQ + GBN - 1) / GBN, MQ / GBM), 256, SMEM_GEMM>>>(
        fh, fl, owh, owl, out_b, logits, nullptr, nullptr, nullptr, 0, 0,
        nullptr, nullptr, CLSQ, DQ, 1, DQ);

    softmax_kernel<<<MQ, 256>>>(logits, logp, p);
    aux_kernel<<<1, 256>>>(aux);
}